// round 3
// baseline (speedup 1.0000x reference)
#include <cuda_runtime.h>
#include <cuda_bf16.h>
#include <math.h>

// Problem constants (fixed shapes for this problem)
#define NROWS 65536
#define DDIM  512
#define CCLS  64

#define GA 128                 // kernel A blocks (65536/128 = 512 rows/block)
#define GC 512                 // kernel C blocks (128 rows each)

// ---------------- device scratch (no allocations allowed) ----------------
__device__ float g_psums[GA * CCLS * DDIM];   // per-block partial class sums (16 MB)
__device__ float g_pcnt [GA * CCLS];          // per-block partial class counts
__device__ float g_protoT[DDIM * CCLS];       // prototypes transposed [d][c]
__device__ float g_p2[CCLS];                  // ||p_c||^2
__device__ float g_bl[GC];                    // per-block loss partial
__device__ float g_ba[GC];                    // per-block accuracy partial

// ---------------- f32x2 packed helpers (sm_103a) ----------------
__device__ __forceinline__ void fma2(unsigned long long& d,
                                     unsigned long long a,
                                     unsigned long long b) {
    asm("fma.rn.f32x2 %0, %1, %2, %0;" : "+l"(d) : "l"(a), "l"(b));
}
__device__ __forceinline__ unsigned long long pack2(float x) {
    unsigned long long r;
    unsigned int u = __float_as_uint(x);
    asm("mov.b64 %0, {%1, %1};" : "=l"(r) : "r"(u));
    return r;
}

// ============================================================
// Kernel A: per-block segment sums into smem [64][512], counts.
// Each thread owns a disjoint 2-float column slice -> race-free RMW.
// ============================================================
__global__ void __launch_bounds__(256)
kA(const float* __restrict__ emb, const int* __restrict__ labels) {
    extern __shared__ float s[];          // 32768 acc + 64 cnt + 512 labels
    float* acc  = s;
    float* cnt  = s + CCLS * DDIM;
    int*   slab = (int*)(s + CCLS * DDIM + CCLS);

    int t = threadIdx.x;
    int base = blockIdx.x * 512;

    // zero accumulators, stage labels (clamped to valid range: turns any
    // dtype surprise into a wrong answer instead of an IMA)
    for (int i = t * 4; i < CCLS * DDIM; i += 256 * 4) {
        *(float4*)(acc + i) = make_float4(0.f, 0.f, 0.f, 0.f);
    }
    if (t < CCLS) cnt[t] = 0.f;
    slab[t]       = labels[base + t] & (CCLS - 1);
    slab[t + 256] = labels[base + t + 256] & (CCLS - 1);
    __syncthreads();

    // counts (smem atomics; integer-valued floats -> exact, order-free)
    atomicAdd(&cnt[slab[t]], 1.f);
    atomicAdd(&cnt[slab[t + 256]], 1.f);

    const float* eBase = emb + (size_t)base * DDIM + t * 2;
#pragma unroll 4
    for (int r = 0; r < 512; r++) {
        float2 v = *(const float2*)(eBase + (size_t)r * DDIM);
        int l = slab[r];
        float2* a = (float2*)(acc + l * DDIM + t * 2);
        float2 c = *a;
        c.x += v.x; c.y += v.y;
        *a = c;
    }
    __syncthreads();

    float* out = g_psums + (size_t)blockIdx.x * (CCLS * DDIM);
    for (int i = t * 4; i < CCLS * DDIM; i += 256 * 4) {
        *(float4*)(out + i) = *(float4*)(acc + i);
    }
    if (t < CCLS) g_pcnt[blockIdx.x * CCLS + t] = cnt[t];
}

// ============================================================
// Kernel B: reduce partials -> protoT [d][c], p2[c]
// one block per class, 512 threads (one per d)
// ============================================================
__global__ void __launch_bounds__(512)
kB() {
    int c = blockIdx.x;
    int d = threadIdx.x;
    __shared__ float scnt[128];
    __shared__ float sred[512];

    if (d < 128) scnt[d] = g_pcnt[d * CCLS + c];
    __syncthreads();
    for (int s = 64; s >= 1; s >>= 1) {
        if (d < s) scnt[d] += scnt[d + s];
        __syncthreads();
    }
    float cnt = scnt[0];

    float sum = 0.f;
    const float* base = g_psums + (size_t)c * DDIM + d;
#pragma unroll 8
    for (int g = 0; g < GA; g++) {
        sum += base[(size_t)g * (CCLS * DDIM)];
    }
    float proto = sum / cnt;
    g_protoT[d * CCLS + c] = proto;

    sred[d] = proto * proto;
    __syncthreads();
    for (int s = 256; s >= 1; s >>= 1) {
        if (d < s) sred[d] += sred[d + s];
        __syncthreads();
    }
    if (d == 0) g_p2[c] = sred[0];
}

// ============================================================
// Kernel C: GEMM 128x64 per block (f32x2 packed FMA) + fused
//           e2, logits, softmax, NLL, argmax, block partials
// ============================================================
#define ASTRIDE 130
// smem float layout:
//   [0 .. 4160)        As[32][130]        (tile phase)
//   [4160 .. 6208)     Bs[32][64]         (tile phase)
//   [0 .. 1024)        e2 partial staging (after mainloop)
//   [0 .. 8704)        logits [128][68]   (epilogue)
//   [8704 .. 8832)     e2[128]
//   [8832 .. 8896)     p2[64]
//   [8896 .. 8904)     warp loss[8]
//   [8904 .. 8912)     warp acc[8]
#define SMC_FLOATS 8912

__global__ void __launch_bounds__(256)
kC(const float* __restrict__ emb, const int* __restrict__ labels) {
    __shared__ float sm[SMC_FLOATS];
    float* SA = sm;
    float* SB = sm + 4160;

    int t  = threadIdx.x;
    int tx = t & 15;      // 16 col groups * 4 cols
    int ty = t >> 4;      // 16 row groups * 8 rows

    unsigned long long acc[4][4];
#pragma unroll
    for (int i = 0; i < 4; i++)
#pragma unroll
        for (int j = 0; j < 4; j++) acc[i][j] = 0ull;

    float e2part[4] = {0.f, 0.f, 0.f, 0.f};

    int arow0 = t >> 3;            // 0..31
    int kq    = t & 7;             // k quarter (4 floats)
    const float* aBase = emb + ((size_t)(blockIdx.x * 128 + arow0)) * DDIM + kq * 4;

    for (int kt = 0; kt < 16; kt++) {
        // ---- load A tile (128 x 32), store transposed with pad 130
        const float* ap = aBase + kt * 32;
#pragma unroll
        for (int i = 0; i < 4; i++) {
            float4 v = *(const float4*)(ap + (size_t)i * 32 * DDIM);
            e2part[i] += v.x * v.x + v.y * v.y + v.z * v.z + v.w * v.w;
            int lrow = arow0 + 32 * i;
            SA[(kq * 4 + 0) * ASTRIDE + lrow] = v.x;
            SA[(kq * 4 + 1) * ASTRIDE + lrow] = v.y;
            SA[(kq * 4 + 2) * ASTRIDE + lrow] = v.z;
            SA[(kq * 4 + 3) * ASTRIDE + lrow] = v.w;
        }
        // ---- load B tile (32 x 64) from protoT
#pragma unroll
        for (int h = 0; h < 2; h++) {
            int kk = (t >> 4) + 16 * h;
            float4 b = *(const float4*)(g_protoT + (size_t)(kt * 32 + kk) * CCLS + (t & 15) * 4);
            *(float4*)&SB[kk * CCLS + (t & 15) * 4] = b;
        }
        __syncthreads();

        // ---- compute
#pragma unroll
        for (int k = 0; k < 32; k++) {
            unsigned long long a[4];
            const float* arow = &SA[k * ASTRIDE + ty * 8];
            a[0] = *(const unsigned long long*)(arow + 0);
            a[1] = *(const unsigned long long*)(arow + 2);
            a[2] = *(const unsigned long long*)(arow + 4);
            a[3] = *(const unsigned long long*)(arow + 6);
            float4 b = *(const float4*)&SB[k * CCLS + tx * 4];
            unsigned long long bb0 = pack2(b.x);
            unsigned long long bb1 = pack2(b.y);
            unsigned long long bb2 = pack2(b.z);
            unsigned long long bb3 = pack2(b.w);
#pragma unroll
            for (int rp = 0; rp < 4; rp++) {
                fma2(acc[rp][0], a[rp], bb0);
                fma2(acc[rp][1], a[rp], bb1);
                fma2(acc[rp][2], a[rp], bb2);
                fma2(acc[rp][3], a[rp], bb3);
            }
        }
        __syncthreads();
    }

    // ---- e2 reduce (deterministic: fixed staging + fixed order)
#pragma unroll
    for (int i = 0; i < 4; i++) {
        sm[(arow0 + 32 * i) * 8 + kq] = e2part[i];
    }
    __syncthreads();
    if (t < 128) {
        float s = 0.f;
#pragma unroll
        for (int j = 0; j < 8; j++) s += sm[t * 8 + j];
        sm[8704 + t] = s;
    }
    if (t < CCLS) sm[8832 + t] = g_p2[t];
    __syncthreads();

    // ---- logits into sm[0 .. 8704): [128][68]
    float p2v[4];
#pragma unroll
    for (int c = 0; c < 4; c++) p2v[c] = sm[8832 + tx * 4 + c];
#pragma unroll
    for (int rp = 0; rp < 4; rp++) {
        int lr = ty * 8 + 2 * rp;
        float e0 = sm[8704 + lr];
        float e1 = sm[8704 + lr + 1];
#pragma unroll
        for (int c = 0; c < 4; c++) {
            float2 cr = *(float2*)&acc[rp][c];
            float d20 = fmaxf(e0 + p2v[c] - 2.f * cr.x, 1e-12f);
            float d21 = fmaxf(e1 + p2v[c] - 2.f * cr.y, 1e-12f);
            sm[lr * 68 + tx * 4 + c]       = -sqrtf(d20);
            sm[(lr + 1) * 68 + tx * 4 + c] = -sqrtf(d21);
        }
    }
    __syncthreads();

    // ---- per-row softmax / NLL / argmax. warp w handles rows w, w+8, ...
    int w = t >> 5, lane = t & 31;
    float lossAcc = 0.f, accAcc = 0.f;
    for (int j = 0; j < 16; j++) {
        int lrow = w + 8 * j;
        float v0 = sm[lrow * 68 + lane];
        float v1 = sm[lrow * 68 + 32 + lane];
        float bv; int bi;
        if (v1 > v0) { bv = v1; bi = lane + 32; } else { bv = v0; bi = lane; }
#pragma unroll
        for (int s = 16; s > 0; s >>= 1) {
            float ov = __shfl_xor_sync(0xffffffffu, bv, s);
            int   oi = __shfl_xor_sync(0xffffffffu, bi, s);
            if (ov > bv || (ov == bv && oi < bi)) { bv = ov; bi = oi; }
        }
        // bv = row max (first-occurrence argmax index bi)
        float e = expf(v0 - bv) + expf(v1 - bv);
#pragma unroll
        for (int s = 16; s > 0; s >>= 1) {
            e += __shfl_xor_sync(0xffffffffu, e, s);
        }
        float lse = bv + logf(e);
        int lab = labels[blockIdx.x * 128 + lrow] & (CCLS - 1);
        float lv = sm[lrow * 68 + lab];
        lossAcc += (lse - lv);
        accAcc  += (bi == lab) ? 1.f : 0.f;
    }
    if (lane == 0) { sm[8896 + w] = lossAcc; sm[8904 + w] = accAcc; }
    __syncthreads();
    if (t == 0) {
        float L = 0.f, A = 0.f;
#pragma unroll
        for (int ww = 0; ww < 8; ww++) { L += sm[8896 + ww]; A += sm[8904 + ww]; }
        g_bl[blockIdx.x] = L;
        g_ba[blockIdx.x] = A;
    }
}

// ============================================================
// Kernel D: final reduce -> out[0]=loss, out[1]=accuracy
// ============================================================
__global__ void __launch_bounds__(512)
kD(float* __restrict__ out) {
    __shared__ float sl[512];
    __shared__ float sa[512];
    int t = threadIdx.x;
    sl[t] = g_bl[t];
    sa[t] = g_ba[t];
    __syncthreads();
    for (int s = 256; s >= 1; s >>= 1) {
        if (t < s) { sl[t] += sl[t + s]; sa[t] += sa[t + s]; }
        __syncthreads();
    }
    if (t == 0) {
        const float invN = 1.f / (float)NROWS;
        out[0] = sl[0] * invN;
        out[1] = sa[0] * invN;
    }
}

// ============================================================
extern "C" void kernel_launch(void* const* d_in, const int* in_sizes, int n_in,
                              void* d_out, int out_size) {
    const float* emb    = (const float*)d_in[0];
    const int*   labels = (const int*)d_in[1];
    float*       out    = (float*)d_out;

    const int smemA = (CCLS * DDIM + CCLS) * (int)sizeof(float)
                    + 512 * (int)sizeof(int);   // acc + cnt + label stage
    cudaFuncSetAttribute(kA, cudaFuncAttributeMaxDynamicSharedMemorySize, smemA);

    kA<<<GA, 256, smemA>>>(emb, labels);
    kB<<<CCLS, 512>>>();
    kC<<<GC, 256>>>(emb, labels);
    kD<<<1, 512>>>(out);
}

// round 6
// speedup vs baseline: 1.2055x; 1.2055x over previous
#include <cuda_runtime.h>
#include <cuda_bf16.h>
#include <cstdint>
#include <math.h>

// Problem constants (fixed shapes)
#define NROWS 65536
#define DDIM  512
#define CCLS  64

#define GA 128                 // kernel A blocks
#define GC 512                 // kernel C blocks (128 rows each)

// ---------------- device scratch ----------------
__device__ float g_psums[GA * CCLS * DDIM];      // per-block partial class sums
__device__ float g_pcnt [GA * CCLS];             // per-block partial class counts
__device__ __nv_bfloat16 g_pHi[CCLS * DDIM];     // prototypes hi (bf16) [c][d]
__device__ __nv_bfloat16 g_pLo[CCLS * DDIM];     // prototypes lo (bf16)
__device__ float g_p2[CCLS];                     // ||p_c||^2 (fp32)
__device__ float g_bl[GC];                       // per-block loss partial
__device__ float g_ba[GC];                       // per-block accuracy partial

// ---------------- helpers ----------------
__device__ __forceinline__ uint32_t smem_u32(const void* p) {
    uint32_t a;
    asm("{ .reg .u64 t; cvta.to.shared.u64 t, %1; cvt.u32.u64 %0, t; }" : "=r"(a) : "l"(p));
    return a;
}
__device__ __forceinline__ uint32_t bf16x2_of(float lo, float hi) {
    uint32_t r;
    asm("cvt.rn.bf16x2.f32 %0, %1, %2;" : "=r"(r) : "f"(hi), "f"(lo));
    return r;
}
__device__ __forceinline__ float hf_lo(uint32_t h) { return __uint_as_float(h << 16); }
__device__ __forceinline__ float hf_hi(uint32_t h) { return __uint_as_float(h & 0xFFFF0000u); }

#define SWZ(off) ((off) ^ (((off) >> 3) & 0x70))

#define STS128(a, r0, r1, r2, r3) \
    asm volatile("st.shared.v4.b32 [%0], {%1,%2,%3,%4};" :: "r"(a), "r"(r0), "r"(r1), "r"(r2), "r"(r3) : "memory")

#define LDSM4(r, a) \
    asm volatile("ldmatrix.sync.aligned.m8n8.x4.shared.b16 {%0,%1,%2,%3}, [%4];" \
        : "=r"((r)[0]), "=r"((r)[1]), "=r"((r)[2]), "=r"((r)[3]) : "r"(a))

__device__ __forceinline__ void mma_bf16(float* d, const uint32_t* a, uint32_t b0, uint32_t b1) {
    asm volatile("mma.sync.aligned.m16n8k16.row.col.f32.bf16.bf16.f32 "
        "{%0,%1,%2,%3}, {%4,%5,%6,%7}, {%8,%9}, {%0,%1,%2,%3};"
        : "+f"(d[0]), "+f"(d[1]), "+f"(d[2]), "+f"(d[3])
        : "r"(a[0]), "r"(a[1]), "r"(a[2]), "r"(a[3]), "r"(b0), "r"(b1));
}

// ============================================================
// Kernel A: per-block segment sums (race-free column slices)
// ============================================================
__global__ void __launch_bounds__(256)
kA(const float* __restrict__ emb, const int* __restrict__ labels) {
    extern __shared__ float s[];
    float* acc  = s;
    float* cnt  = s + CCLS * DDIM;
    int*   slab = (int*)(s + CCLS * DDIM + CCLS);

    int t = threadIdx.x;
    int base = blockIdx.x * 512;

    for (int i = t * 4; i < CCLS * DDIM; i += 256 * 4)
        *(float4*)(acc + i) = make_float4(0.f, 0.f, 0.f, 0.f);
    if (t < CCLS) cnt[t] = 0.f;
    slab[t]       = labels[base + t] & (CCLS - 1);
    slab[t + 256] = labels[base + t + 256] & (CCLS - 1);
    __syncthreads();

    atomicAdd(&cnt[slab[t]], 1.f);
    atomicAdd(&cnt[slab[t + 256]], 1.f);

    const float* eBase = emb + (size_t)base * DDIM + t * 2;
#pragma unroll 4
    for (int r = 0; r < 512; r++) {
        float2 v = *(const float2*)(eBase + (size_t)r * DDIM);
        int l = slab[r];
        float2* a = (float2*)(acc + l * DDIM + t * 2);
        float2 c = *a;
        c.x += v.x; c.y += v.y;
        *a = c;
    }
    __syncthreads();

    float* out = g_psums + (size_t)blockIdx.x * (CCLS * DDIM);
    for (int i = t * 4; i < CCLS * DDIM; i += 256 * 4)
        *(float4*)(out + i) = *(float4*)(acc + i);
    if (t < CCLS) g_pcnt[blockIdx.x * CCLS + t] = cnt[t];
}

// ============================================================
// Kernel B: reduce partials -> prototypes (bf16 hi/lo) + p2
// ============================================================
__global__ void __launch_bounds__(512)
kB() {
    int c = blockIdx.x;
    int d = threadIdx.x;
    __shared__ float scnt[128];
    __shared__ float sred[512];

    if (d < 128) scnt[d] = g_pcnt[d * CCLS + c];
    __syncthreads();
    for (int s = 64; s >= 1; s >>= 1) {
        if (d < s) scnt[d] += scnt[d + s];
        __syncthreads();
    }
    float cnt = scnt[0];

    float sum = 0.f;
    const float* base = g_psums + (size_t)c * DDIM + d;
#pragma unroll 8
    for (int g = 0; g < GA; g++) sum += base[(size_t)g * (CCLS * DDIM)];
    float proto = sum / cnt;

    __nv_bfloat16 h = __float2bfloat16(proto);
    float hf = __bfloat162float(h);
    g_pHi[c * DDIM + d] = h;
    g_pLo[c * DDIM + d] = __float2bfloat16(proto - hf);

    sred[d] = proto * proto;
    __syncthreads();
    for (int s = 256; s >= 1; s >>= 1) {
        if (d < s) sred[d] += sred[d + s];
        __syncthreads();
    }
    if (d == 0) g_p2[c] = sred[0];
}

// ============================================================
// Kernel C: HMMA (mma.sync bf16 hi/lo) GEMM 128x64 per CTA over
//           K=512 in 8 chunks + fused softmax/NLL/argmax
// ============================================================
// smem byte offsets (from 1024-aligned base):
#define OFF_AHI   0            // 128x64 bf16 = 16KB
#define OFF_ALO   16384
#define OFF_BHI   32768        // 64x64 bf16 = 8KB
#define OFF_BLO   40960
//   stage total 49152; logits [128][68] f32 = 34816 reuses [0..)
#define OFF_LOG   0
#define OFF_E2    49152        // 256 floats (per (row,half) partials)
#define OFF_P2    50176        // 64 floats
#define OFF_WL    50432        // 8 floats
#define OFF_WA    50464        // 8 floats
#define SMC_BYTES (50496 + 1024)

__global__ void __launch_bounds__(256, 2)
kC(const float* __restrict__ emb, const int* __restrict__ labels) {
    extern __shared__ __align__(16) unsigned char smraw[];
    uint32_t raw = smem_u32(smraw);
    uint32_t base = (raw + 1023) & ~1023u;
    float* smf = (float*)(smraw + (base - raw));   // float view of aligned base

    const int t = threadIdx.x;
    const int wid = t >> 5, lane = t & 31;
    const int blk = blockIdx.x;

    const int Rb = (wid >> 1) * 32;   // warp row base (0..96)
    const int Cb = (wid & 1) * 32;    // warp col base (0 or 32)

    const int row  = t >> 1;          // 0..127 (A loader row)
    const int half = t & 1;           // 32-col half
    const float* aptr = emb + ((size_t)(blk * 128 + row)) * DDIM + half * 32;
    float e2acc = 0.f;

    float acc[2][4][4];
#pragma unroll
    for (int i = 0; i < 2; i++)
#pragma unroll
        for (int j = 0; j < 4; j++)
#pragma unroll
            for (int k = 0; k < 4; k++) acc[i][j][k] = 0.f;

    // per-lane ldmatrix offsets (constant across chunks except ks/k)
    const int arowoff = (lane & 7) + ((lane >> 3) & 1) * 8;
    const int akoff   = ((lane >> 4) & 1) * 8;
    const int bnoff   = (lane & 7) + ((lane >> 4) & 1) * 8;
    const int bkoff   = ((lane >> 3) & 1) * 8;

    for (int kt = 0; kt < 8; kt++) {
        // ---- A: load 32 f32, convert to bf16 hi/lo, swizzled STS
        float4 av[8];
#pragma unroll
        for (int i = 0; i < 8; i++) av[i] = *(const float4*)(aptr + kt * 64 + i * 4);
        // ---- B: copy hi/lo chunk rows
        uint4 bhv[2], blv[2];
#pragma unroll
        for (int i = 0; i < 2; i++) {
            int chunk = t * 2 + i;          // 0..511
            int brow = chunk >> 3;          // class 0..63
            int bcg  = chunk & 7;           // 16B chunk in 128B row
            size_t go = (size_t)brow * DDIM + kt * 64 + bcg * 8;
            bhv[i] = *(const uint4*)(g_pHi + go);
            blv[i] = *(const uint4*)(g_pLo + go);
        }

#pragma unroll
        for (int j = 0; j < 4; j++) {
            float4 v0 = av[2 * j], v1 = av[2 * j + 1];
            e2acc += v0.x * v0.x + v0.y * v0.y + v0.z * v0.z + v0.w * v0.w
                   + v1.x * v1.x + v1.y * v1.y + v1.z * v1.z + v1.w * v1.w;
            uint32_t h0 = bf16x2_of(v0.x, v0.y);
            uint32_t h1 = bf16x2_of(v0.z, v0.w);
            uint32_t h2 = bf16x2_of(v1.x, v1.y);
            uint32_t h3 = bf16x2_of(v1.z, v1.w);
            uint32_t l0 = bf16x2_of(v0.x - hf_lo(h0), v0.y - hf_hi(h0));
            uint32_t l1 = bf16x2_of(v0.z - hf_lo(h1), v0.w - hf_hi(h1));
            uint32_t l2 = bf16x2_of(v1.x - hf_lo(h2), v1.y - hf_hi(h2));
            uint32_t l3 = bf16x2_of(v1.z - hf_lo(h3), v1.w - hf_hi(h3));
            uint32_t boff = (uint32_t)(row * 128 + half * 64 + j * 16);
            uint32_t sw = SWZ(boff);
            STS128(base + OFF_AHI + sw, h0, h1, h2, h3);
            STS128(base + OFF_ALO + sw, l0, l1, l2, l3);
        }
#pragma unroll
        for (int i = 0; i < 2; i++) {
            int chunk = t * 2 + i;
            int brow = chunk >> 3, bcg = chunk & 7;
            uint32_t sw = SWZ((uint32_t)(brow * 128 + bcg * 16));
            STS128(base + OFF_BHI + sw, bhv[i].x, bhv[i].y, bhv[i].z, bhv[i].w);
            STS128(base + OFF_BLO + sw, blv[i].x, blv[i].y, blv[i].z, blv[i].w);
        }
        __syncthreads();

        // ---- compute: 4 k16 steps
#pragma unroll
        for (int ks = 0; ks < 4; ks++) {
            uint32_t ah[2][4], al[2][4];
#pragma unroll
            for (int mt = 0; mt < 2; mt++) {
                uint32_t off = (uint32_t)((Rb + 16 * mt + arowoff) * 128 + (ks * 16 + akoff) * 2);
                uint32_t sw = SWZ(off);
                LDSM4(ah[mt], base + OFF_AHI + sw);
                LDSM4(al[mt], base + OFF_ALO + sw);
            }
            uint32_t bh[2][4], bl[2][4];
#pragma unroll
            for (int p = 0; p < 2; p++) {
                uint32_t off = (uint32_t)((Cb + 16 * p + bnoff) * 128 + (ks * 16 + bkoff) * 2);
                uint32_t sw = SWZ(off);
                LDSM4(bh[p], base + OFF_BHI + sw);
                LDSM4(bl[p], base + OFF_BLO + sw);
            }
#pragma unroll
            for (int mt = 0; mt < 2; mt++)
#pragma unroll
                for (int p = 0; p < 2; p++)
#pragma unroll
                    for (int q = 0; q < 2; q++) {
                        float* d = acc[mt][2 * p + q];
                        mma_bf16(d, ah[mt], bh[p][2 * q], bh[p][2 * q + 1]);
                        mma_bf16(d, ah[mt], bl[p][2 * q], bl[p][2 * q + 1]);
                        mma_bf16(d, al[mt], bh[p][2 * q], bh[p][2 * q + 1]);
                    }
        }
        __syncthreads();
    }

    // ---- stage e2 partials and p2
    float* e2p = smf + OFF_E2 / 4;
    float* p2s = smf + OFF_P2 / 4;
    float* wl  = smf + OFF_WL / 4;
    float* wa  = smf + OFF_WA / 4;
    e2p[t] = e2acc;
    if (t < CCLS) p2s[t] = g_p2[t];
    __syncthreads();

    // ---- logits into smf[0 .. 128*68)
    {
        int g  = lane >> 2;
        int tq = lane & 3;
#pragma unroll
        for (int mt = 0; mt < 2; mt++) {
            int r0 = Rb + 16 * mt + g;
            float e2a = e2p[2 * r0] + e2p[2 * r0 + 1];
            float e2b = e2p[2 * (r0 + 8)] + e2p[2 * (r0 + 8) + 1];
#pragma unroll
            for (int nt = 0; nt < 4; nt++) {
                int col = Cb + 8 * nt + 2 * tq;
                float p2a = p2s[col], p2b = p2s[col + 1];
                float* d = acc[mt][nt];
                float lg0 = -sqrtf(fmaxf(e2a + p2a - 2.f * d[0], 1e-12f));
                float lg1 = -sqrtf(fmaxf(e2a + p2b - 2.f * d[1], 1e-12f));
                float lg2 = -sqrtf(fmaxf(e2b + p2a - 2.f * d[2], 1e-12f));
                float lg3 = -sqrtf(fmaxf(e2b + p2b - 2.f * d[3], 1e-12f));
                *(float2*)&smf[r0 * 68 + col]       = make_float2(lg0, lg1);
                *(float2*)&smf[(r0 + 8) * 68 + col] = make_float2(lg2, lg3);
            }
        }
    }
    __syncthreads();

    // ---- per-row softmax / NLL / argmax; warp w rows w, w+8, ...
    float lossAcc = 0.f, accAcc = 0.f;
    for (int j = 0; j < 16; j++) {
        int lrow = wid + 8 * j;
        float v0 = smf[lrow * 68 + lane];
        float v1 = smf[lrow * 68 + 32 + lane];
        float bv; int bi;
        if (v1 > v0) { bv = v1; bi = lane + 32; } else { bv = v0; bi = lane; }
#pragma unroll
        for (int s = 16; s > 0; s >>= 1) {
            float ov = __shfl_xor_sync(0xffffffffu, bv, s);
            int   oi = __shfl_xor_sync(0xffffffffu, bi, s);
            if (ov > bv || (ov == bv && oi < bi)) { bv = ov; bi = oi; }
        }
        float e = expf(v0 - bv) + expf(v1 - bv);
#pragma unroll
        for (int s = 16; s > 0; s >>= 1)
            e += __shfl_xor_sync(0xffffffffu, e, s);
        float lse = bv + logf(e);
        int lab = labels[blk * 128 + lrow] & (CCLS - 1);
        float lv = smf[lrow * 68 + lab];
        lossAcc += (lse - lv);
        accAcc  += (bi == lab) ? 1.f : 0.f;
    }
    if (lane == 0) { wl[wid] = lossAcc; wa[wid] = accAcc; }
    __syncthreads();
    if (t == 0) {
        float L = 0.f, A = 0.f;
#pragma unroll
        for (int ww = 0; ww < 8; ww++) { L += wl[ww]; A += wa[ww]; }
        g_bl[blk] = L;
        g_ba[blk] = A;
    }
}

// ============================================================
// Kernel D: final reduce -> out[0]=loss, out[1]=accuracy
// ============================================================
__global__ void __launch_bounds__(512)
kD(float* __restrict__ out) {
    __shared__ float sl[512];
    __shared__ float sa[512];
    int t = threadIdx.x;
    sl[t] = g_bl[t];
    sa[t] = g_ba[t];
    __syncthreads();
    for (int s = 256; s >= 1; s >>= 1) {
        if (t < s) { sl[t] += sl[t + s]; sa[t] += sa[t + s]; }
        __syncthreads();
    }
    if (t == 0) {
        const float invN = 1.f / (float)NROWS;
        out[0] = sl[0] * invN;
        out[1] = sa[0] * invN;
    }
}

// ============================================================
extern "C" void kernel_launch(void* const* d_in, const int* in_sizes, int n_in,
                              void* d_out, int out_size) {
    const float* emb    = (const float*)d_in[0];
    const int*   labels = (const int*)d_in[1];
    float*       out    = (float*)d_out;

    const int smemA = (CCLS * DDIM + CCLS) * (int)sizeof(float) + 512 * (int)sizeof(int);
    cudaFuncSetAttribute(kA, cudaFuncAttributeMaxDynamicSharedMemorySize, smemA);
    cudaFuncSetAttribute(kC, cudaFuncAttributeMaxDynamicSharedMemorySize, SMC_BYTES);

    kA<<<GA, 256, smemA>>>(emb, labels);
    kB<<<CCLS, 512>>>();
    kC<<<GC, 256, SMC_BYTES>>>(emb, labels);
    kD<<<1, 512>>>(out);
}